// round 4
// baseline (speedup 1.0000x reference)
#include <cuda_runtime.h>
#include <cstddef>

#define B_    4096
#define T_    128
#define NL_   256
#define NS_   64
#define NO_   32
#define V_    64

#define ROWS_ 32      // batch rows per CTA
#define NTH_  512     // 16 warps
#define KB_   64      // K per W1 chunk
#define NCH_  4       // chunks per step
#define XP_   260     // latent tile pitch (floats): 1040B rows, 16B aligned
#define WP_   68      // W1 stage pitch (floats): 272B rows, 16B aligned, conflict-free phases

typedef unsigned long long u64;

__device__ __forceinline__ u64 ffma2(u64 a, u64 b, u64 c) {
    u64 d;
    asm("fma.rn.f32x2 %0, %1, %2, %3;" : "=l"(d) : "l"(a), "l"(b), "l"(c));
    return d;
}

__device__ __forceinline__ void cp16(float* dst_smem, const float* src) {
    unsigned int d = (unsigned int)__cvta_generic_to_shared(dst_smem);
    asm volatile("cp.async.cg.shared.global [%0], [%1], 16;" :: "r"(d), "l"(src) : "memory");
}

// Stage one 256xKB_ chunk of W1[s] (verbatim, pitch WP_): 4096 float4, 8 per thread.
__device__ __forceinline__ void stage_chunk(const float* W1s, int kb, float* ws, int tid) {
    #pragma unroll
    for (int q = 0; q < 8; ++q) {
        int g  = tid + NTH_ * q;        // 0..4095
        int j  = g >> 4;                // row 0..255 (16 float4 per row)
        int c4 = (g & 15) << 2;         // 0,4,...,60
        cp16(ws + j * WP_ + c4, W1s + (size_t)j * NL_ + kb + c4);
    }
    asm volatile("cp.async.commit_group;" ::: "memory");
}

// Dynamic smem (floats):
//   xA[32*260], xB[32*260]   latent ping/pong
//   wsA[256*68], wsB[256*68] W1 chunk double buffer (wsB reused as W2 stage, pitch 260)
//   yb[32*64]                scatter rows
//   seq[128] (int)
__global__ void __launch_bounds__(NTH_, 1)
lalr_persistent_kernel(const float* __restrict__ latent0,
                       const float* __restrict__ W1,
                       const float* __restrict__ b1,
                       const float* __restrict__ W2,
                       const float* __restrict__ b2,
                       const int*   __restrict__ state_seq,
                       const int*   __restrict__ out_idx,
                       float*       __restrict__ out)
{
    extern __shared__ float sm[];
    float* xA  = sm;
    float* xB  = xA  + ROWS_ * XP_;
    float* wsA = xB  + ROWS_ * XP_;
    float* wsB = wsA + 256 * WP_;
    float* yb  = wsB + 256 * WP_;
    int*   seq = (int*)(yb + ROWS_ * V_);

    const int tid  = threadIdx.x;
    const int w    = tid >> 5;
    const int lane = tid & 31;
    const int r0   = blockIdx.x * ROWS_;

    const int rb  = (w >> 2) * 8;      // phase-1 rows rb..rb+7   (4 row groups)
    const int jb  = (w & 3) * 64;      // phase-1 col quarter     (4 col groups)
    const int rw2 = w * 2;             // phase-2 rows rw2..rw2+1

    if (tid < T_) seq[tid] = state_seq[tid];

    for (int i = tid; i < ROWS_ * NL_; i += NTH_) {
        int r = i >> 8;
        int k = i & (NL_ - 1);
        xA[r * XP_ + k] = latent0[(size_t)(r0 + r) * NL_ + k];
    }

    // Prologue: stage chunk 0 of step 0 into wsA.
    stage_chunk(W1 + (size_t)state_seq[0] * (NL_ * NL_), 0, wsA, tid);
    __syncthreads();

    float* xcur = xA;
    float* xnew = xB;

    for (int t = 0; t < T_; ++t) {
        const int s = seq[t];
        const float* W1s = W1 + (size_t)s * (NL_ * NL_);

        // ------------- Phase 1: x_new = tanh(x @ W1[s]^T + b1[s]) -------------
        u64 acc[8][2];
        #pragma unroll
        for (int i = 0; i < 8; ++i) { acc[i][0] = 0ull; acc[i][1] = 0ull; }

        for (int c = 0; c < NCH_; ++c) {
            // Prefetch next chunk (c==NCH_-1 -> next step's chunk 0).
            {
                const float* Wn; int kbn;
                int cn = c + 1;
                if (cn < NCH_) { Wn = W1s; kbn = cn * KB_; }
                else {
                    int sn = (t < T_ - 1) ? seq[t + 1] : s;
                    Wn = W1 + (size_t)sn * (NL_ * NL_); kbn = 0;
                }
                stage_chunk(Wn, kbn, (cn & 1) ? wsB : wsA, tid);
            }
            asm volatile("cp.async.wait_group 1;" ::: "memory");
            __syncthreads();

            const float* ws = (c & 1) ? wsB : wsA;
            const int kb = c * KB_;

            #pragma unroll 4
            for (int m4 = 0; m4 < KB_ / 4; ++m4) {
                ulonglong2 xq[8];
                #pragma unroll
                for (int i = 0; i < 8; ++i)
                    xq[i] = *(const ulonglong2*)(xcur + (rb + i) * XP_ + kb + 4 * m4);
                ulonglong2 wq0 = *(const ulonglong2*)(ws + (jb + lane)      * WP_ + 4 * m4);
                ulonglong2 wq1 = *(const ulonglong2*)(ws + (jb + lane + 32) * WP_ + 4 * m4);
                #pragma unroll
                for (int i = 0; i < 8; ++i) {
                    acc[i][0] = ffma2(xq[i].x, wq0.x, acc[i][0]);
                    acc[i][0] = ffma2(xq[i].y, wq0.y, acc[i][0]);
                    acc[i][1] = ffma2(xq[i].x, wq1.x, acc[i][1]);
                    acc[i][1] = ffma2(xq[i].y, wq1.y, acc[i][1]);
                }
            }
            __syncthreads();   // everyone done with buf[c&1] before it is restaged
        }

        // Stage W2[s] (32x256 -> wsB pitch XP_) overlapped with tanh epilogue.
        // wsB's chunk (c=3) was fully consumed at the barrier above.
        #pragma unroll
        for (int q = 0; q < 4; ++q) {
            int idx4 = tid + q * NTH_;             // 0..2047
            int o    = idx4 >> 6;
            int k4   = (idx4 & 63) << 2;
            cp16(wsB + o * XP_ + k4, W2 + ((size_t)s * NO_ + o) * NL_ + k4);
        }
        asm volatile("cp.async.commit_group;" ::: "memory");

        // bias + tanh -> xnew
        #pragma unroll
        for (int v = 0; v < 2; ++v) {
            int j = jb + lane + 32 * v;
            float bb = __ldg(b1 + s * NL_ + j);
            #pragma unroll
            for (int i = 0; i < 8; ++i) {
                float lo = __uint_as_float((unsigned)acc[i][v]);
                float hi = __uint_as_float((unsigned)(acc[i][v] >> 32));
                xnew[(rb + i) * XP_ + j] = tanhf(lo + hi + bb);
            }
        }
        asm volatile("cp.async.wait_group 0;" ::: "memory");  // W2 (and next chunk0) landed
        __syncthreads();                                      // xnew + W2 visible to all

        // ------------- Phase 2: probs = softmax(x_new @ W2[s]^T + b2[s]) -------
        u64 a2[2] = {0ull, 0ull};
        {
            const ulonglong2* wr = (const ulonglong2*)(wsB + lane * XP_);
            const ulonglong2* x0 = (const ulonglong2*)(xnew + (rw2 + 0) * XP_);
            const ulonglong2* x1 = (const ulonglong2*)(xnew + (rw2 + 1) * XP_);
            #pragma unroll 8
            for (int k4 = 0; k4 < NL_ / 4; ++k4) {
                ulonglong2 wv = wr[k4];
                ulonglong2 v0 = x0[k4];
                a2[0] = ffma2(wv.x, v0.x, a2[0]); a2[0] = ffma2(wv.y, v0.y, a2[0]);
                ulonglong2 v1 = x1[k4];
                a2[1] = ffma2(wv.x, v1.x, a2[1]); a2[1] = ffma2(wv.y, v1.y, a2[1]);
            }
        }

        const float bb2  = __ldg(b2 + s * NO_ + lane);
        const int   idxv = __ldg(out_idx + s * NO_ + lane);
        const unsigned mm = __match_any_sync(0xffffffffu, idxv);
        const bool winner = (lane == (31 - __clz(mm)));

        #pragma unroll
        for (int i = 0; i < 2; ++i) {
            float lo = __uint_as_float((unsigned)a2[i]);
            float hi = __uint_as_float((unsigned)(a2[i] >> 32));
            float v  = lo + hi + bb2;

            float m = v;
            #pragma unroll
            for (int d = 16; d > 0; d >>= 1)
                m = fmaxf(m, __shfl_xor_sync(0xffffffffu, m, d));
            float e = expf(v - m);
            float ssum = e;
            #pragma unroll
            for (int d = 16; d > 0; d >>= 1)
                ssum += __shfl_xor_sync(0xffffffffu, ssum, d);
            float p = e / ssum;

            float* yrow = yb + (rw2 + i) * V_;
            yrow[lane]      = 0.0f;
            yrow[lane + 32] = 0.0f;
            __syncwarp();
            if (winner) yrow[idxv] = p;
            __syncwarp();
            float2 o2 = *(const float2*)(yrow + lane * 2);
            *(float2*)(out + ((size_t)(r0 + rw2 + i) * T_ + t) * V_ + lane * 2) = o2;
        }
        __syncthreads();   // phase2 done with wsB/xnew before next step restages

        float* tmp = xcur; xcur = xnew; xnew = tmp;
    }
}

extern "C" void kernel_launch(void* const* d_in, const int* in_sizes, int n_in,
                              void* d_out, int out_size)
{
    const float* latent0   = (const float*)d_in[0];
    const float* W1        = (const float*)d_in[1];
    const float* b1        = (const float*)d_in[2];
    const float* W2        = (const float*)d_in[3];
    const float* b2        = (const float*)d_in[4];
    const int*   state_seq = (const int*)  d_in[5];
    const int*   out_idx   = (const int*)  d_in[6];
    float*       out       = (float*)      d_out;

    const int smem_bytes = (2 * ROWS_ * XP_ + 2 * 256 * WP_ + ROWS_ * V_) * (int)sizeof(float)
                         + T_ * (int)sizeof(int);   // 214,528 B

    cudaFuncSetAttribute(lalr_persistent_kernel,
                         cudaFuncAttributeMaxDynamicSharedMemorySize, smem_bytes);

    lalr_persistent_kernel<<<B_ / ROWS_, NTH_, smem_bytes>>>(
        latent0, W1, b1, W2, b2, state_seq, out_idx, out);
}